// round 1
// baseline (speedup 1.0000x reference)
#include <cuda_runtime.h>
#include <cstdint>

#define L_SEQ 4096
#define BATCH 256
#define NORD  64
#define TCH   16
#define CCH   256   // L_SEQ / TCH
#define BS3   128   // batch per phase-3 CTA
#define G3    2     // BATCH / BS3

// Scratch (static device globals: no allocations allowed)
__device__ float g_P[(size_t)CCH * NORD * NORD];   // [c][j][i] = P_c[i][j] (transposed)  4 MB
__device__ float g_S[(size_t)CCH * BATCH * NORD];  // [c][b][i] chunk source terms       16 MB
__device__ float g_X[(size_t)CCH * BATCH * NORD];  // [c][b][i] chunk boundary states    16 MB

// ---------------------------------------------------------------------------
// Phase 1: per chunk c, compute (backward over t):
//   w_t = (Prod_{tau>t} A_tau) B_t   and   P_c = Prod_t A_t
// then S_c[b] = sum_t inputs[t,b] * w_t.
// P kept TRANSPOSED in smem: Pt[k][i] = P[i][k]  (conflict-free float4 access)
// ---------------------------------------------------------------------------
__global__ __launch_bounds__(256) void phase1_kernel(
    const float* __restrict__ A, const float* __restrict__ Bv,
    const float* __restrict__ inp)
{
    __shared__ float Pt[NORD * NORD];
    __shared__ float As[NORD * NORD];
    __shared__ float W[TCH][NORD];

    const int c = blockIdx.x, tid = threadIdx.x;
    const int t0 = c * TCH;

    // init: Pt = transpose(A[t0+T-1]); W[T-1] = B-vector at t0+T-1
    {
        const float* Aend = A + (size_t)(t0 + TCH - 1) * (NORD * NORD);
        for (int idx = tid; idx < NORD * NORD; idx += 256) {
            int k = idx >> 6, i = idx & 63;
            Pt[idx] = Aend[i * NORD + k];   // Pt[k][i] = A[i][k]
        }
        if (tid < NORD) W[TCH - 1][tid] = Bv[(size_t)(t0 + TCH - 1) * NORD + tid];
    }
    __syncthreads();

    const int ri = (tid & 15) * 4;   // i-tile
    const int cj = (tid >> 4) * 4;   // j-tile

    #pragma unroll 1
    for (int t = TCH - 2; t >= 0; --t) {
        // stage A_t (row-major) into smem
        {
            const float4* At4 = (const float4*)(A + (size_t)(t0 + t) * (NORD * NORD));
            float4* As4 = (float4*)As;
            for (int idx = tid; idx < (NORD * NORD) / 4; idx += 256) As4[idx] = At4[idx];
        }
        __syncthreads();

        // w_t[i] = sum_k Pt[k][i] * B_t[k]   (uses P BEFORE update => suffix product)
        float wacc = 0.f;
        if (tid < NORD) {
            const float* Bt = Bv + (size_t)(t0 + t) * NORD;
            #pragma unroll
            for (int k = 0; k < NORD; k++) wacc += Pt[k * NORD + tid] * Bt[k];
        }

        // Qt[j][i] = sum_k Pt[k][i] * A_t[k][j]   (i.e. P <- P @ A_t, kept transposed)
        float acc[4][4];
        #pragma unroll
        for (int jj = 0; jj < 4; jj++)
            #pragma unroll
            for (int ii = 0; ii < 4; ii++) acc[jj][ii] = 0.f;

        #pragma unroll
        for (int k = 0; k < NORD; k++) {
            float4 p = *(const float4*)&Pt[k * NORD + ri];
            float4 a = *(const float4*)&As[k * NORD + cj];
            float pv[4] = {p.x, p.y, p.z, p.w};
            float av[4] = {a.x, a.y, a.z, a.w};
            #pragma unroll
            for (int jj = 0; jj < 4; jj++)
                #pragma unroll
                for (int ii = 0; ii < 4; ii++) acc[jj][ii] += av[jj] * pv[ii];
        }
        __syncthreads();           // everyone finished reading Pt

        if (tid < NORD) W[t][tid] = wacc;
        #pragma unroll
        for (int jj = 0; jj < 4; jj++)
            *(float4*)&Pt[(cj + jj) * NORD + ri] =
                make_float4(acc[jj][0], acc[jj][1], acc[jj][2], acc[jj][3]);
        __syncthreads();
    }

    // write P_c (transposed layout, matches phase-2 consumption)
    {
        float4* dst = (float4*)(g_P + (size_t)c * NORD * NORD);
        const float4* src = (const float4*)Pt;
        for (int idx = tid; idx < (NORD * NORD) / 4; idx += 256) dst[idx] = src[idx];
    }

    // S_c[b][i] = sum_t W[t][i] * inputs[t0+t][b]   (thread = batch b)
    {
        float u[TCH];
        #pragma unroll
        for (int tt = 0; tt < TCH; tt++) u[tt] = inp[(size_t)(t0 + tt) * BATCH + tid];
        float* sp = g_S + ((size_t)c * BATCH + tid) * NORD;
        #pragma unroll 1
        for (int i0 = 0; i0 < NORD; i0 += 4) {
            float s0 = 0.f, s1 = 0.f, s2 = 0.f, s3 = 0.f;
            #pragma unroll
            for (int tt = 0; tt < TCH; tt++) {
                float uv = u[tt];
                s0 += W[tt][i0 + 0] * uv;
                s1 += W[tt][i0 + 1] * uv;
                s2 += W[tt][i0 + 2] * uv;
                s3 += W[tt][i0 + 3] * uv;
            }
            *(float4*)(sp + i0) = make_float4(s0, s1, s2, s3);
        }
    }
}

// ---------------------------------------------------------------------------
// Phase 2: sequential over chunks:  X_c = P_c @ X_{c-1} + S_c
// grid = 64 CTAs x 4 batches, 256 threads (thread = (b, i))
// ---------------------------------------------------------------------------
__global__ __launch_bounds__(256) void phase2_kernel()
{
    __shared__ float Ps[NORD * NORD];   // transposed: Ps[j][i] = P[i][j]
    __shared__ float xsm[4][NORD];

    const int tid = threadIdx.x;
    const int b0 = blockIdx.x * 4;
    const int bb = tid >> 6, ii = tid & 63;

    xsm[bb][ii] = 0.f;
    __syncthreads();

    #pragma unroll 1
    for (int c = 0; c < CCH; c++) {
        const float4* gp4 = (const float4*)(g_P + (size_t)c * NORD * NORD);
        float4* ps4 = (float4*)Ps;
        #pragma unroll
        for (int q = 0; q < 4; q++) ps4[tid + q * 256] = gp4[tid + q * 256];
        __syncthreads();

        float acc = g_S[((size_t)c * BATCH + b0 + bb) * NORD + ii];
        #pragma unroll
        for (int j = 0; j < NORD; j++) acc += Ps[j * NORD + ii] * xsm[bb][j];
        __syncthreads();

        xsm[bb][ii] = acc;
        g_X[((size_t)c * BATCH + b0 + bb) * NORD + ii] = acc;
        __syncthreads();
    }
}

// ---------------------------------------------------------------------------
// Phase 3: per (chunk, batch-half): scan T steps with correct init X_{c-1},
// writing all outputs. Per-step GEMM: Xnew(64 x 128) = A_t @ X + B_t (x) u_t.
// 128 threads, 8x8 register tiles. A transposed in smem (pad 68 for conflicts).
// ---------------------------------------------------------------------------
#define P3_APAD 68
#define P3_SMEM ((NORD * P3_APAD + NORD * BS3 + NORD) * 4)

__global__ __launch_bounds__(128) void phase3_kernel(
    const float* __restrict__ A, const float* __restrict__ Bv,
    const float* __restrict__ inp, float* __restrict__ out)
{
    extern __shared__ float sm[];
    float* As = sm;                       // [64][68]  As[k][i] = A[i][k]
    float* xs = sm + NORD * P3_APAD;      // [64][128] xs[j][b]
    float* Bs = xs + NORD * BS3;          // [64]

    const int c  = blockIdx.x >> 1;
    const int b0 = (blockIdx.x & 1) * BS3;
    const int tid = threadIdx.x;
    const int bi = (tid & 15) * 8;        // batch tile
    const int riq = (tid >> 4);           // row tile index
    const int ri = riq * 8;
    const int t0 = c * TCH;

    // load initial state (transposed into [j][b])
    if (c == 0) {
        for (int idx = tid; idx < NORD * BS3; idx += 128) xs[idx] = 0.f;
    } else {
        const float4* Xp = (const float4*)(g_X + (((size_t)(c - 1)) * BATCH + b0 + tid) * NORD);
        #pragma unroll
        for (int j4 = 0; j4 < 16; j4++) {
            float4 v = Xp[j4];
            xs[(j4 * 4 + 0) * BS3 + tid] = v.x;
            xs[(j4 * 4 + 1) * BS3 + tid] = v.y;
            xs[(j4 * 4 + 2) * BS3 + tid] = v.z;
            xs[(j4 * 4 + 3) * BS3 + tid] = v.w;
        }
    }

    #pragma unroll 1
    for (int t = 0; t < TCH; t++) {
        // stage A_t transposed + B_t
        {
            const float* At = A + (size_t)(t0 + t) * (NORD * NORD);
            for (int idx = tid; idx < NORD * NORD; idx += 128) {
                int i = idx >> 6, j = idx & 63;
                As[j * P3_APAD + i] = At[idx];
            }
            if (tid < 16)
                ((float4*)Bs)[tid] = ((const float4*)(Bv + (size_t)(t0 + t) * NORD))[tid];
        }
        __syncthreads();

        float acc[8][8];
        #pragma unroll
        for (int r = 0; r < 8; r++)
            #pragma unroll
            for (int q = 0; q < 8; q++) acc[r][q] = 0.f;

        const float4* As4 = (const float4*)As;
        const float4* xs4 = (const float4*)xs;
        const int ai = (P3_APAD / 4);
        #pragma unroll 16
        for (int k = 0; k < NORD; k++) {
            float4 a0 = As4[k * ai + riq * 2];
            float4 a1 = As4[k * ai + riq * 2 + 1];
            float4 x0 = xs4[k * (BS3 / 4) + (bi >> 2)];
            float4 x1 = xs4[k * (BS3 / 4) + (bi >> 2) + 1];
            float av[8] = {a0.x, a0.y, a0.z, a0.w, a1.x, a1.y, a1.z, a1.w};
            float xv[8] = {x0.x, x0.y, x0.z, x0.w, x1.x, x1.y, x1.z, x1.w};
            #pragma unroll
            for (int r = 0; r < 8; r++)
                #pragma unroll
                for (int q = 0; q < 8; q++) acc[r][q] += av[r] * xv[q];
        }

        // + B_t[i] * u_t[b]
        {
            const float* up = inp + (size_t)(t0 + t) * BATCH + b0 + bi;
            float4 u0 = *(const float4*)up;
            float4 u1 = *(const float4*)(up + 4);
            float uu[8] = {u0.x, u0.y, u0.z, u0.w, u1.x, u1.y, u1.z, u1.w};
            float bvv[8];
            #pragma unroll
            for (int r = 0; r < 8; r++) bvv[r] = Bs[ri + r];
            #pragma unroll
            for (int r = 0; r < 8; r++)
                #pragma unroll
                for (int q = 0; q < 8; q++) acc[r][q] += bvv[r] * uu[q];
        }
        __syncthreads();   // all threads done reading xs/As

        // update state + write output x_t
        #pragma unroll
        for (int r = 0; r < 8; r++) {
            *(float4*)&xs[(ri + r) * BS3 + bi]     = make_float4(acc[r][0], acc[r][1], acc[r][2], acc[r][3]);
            *(float4*)&xs[(ri + r) * BS3 + bi + 4] = make_float4(acc[r][4], acc[r][5], acc[r][6], acc[r][7]);
        }
        float* op = out + (size_t)(t0 + t) * (BATCH * NORD) + (size_t)(b0 + bi) * NORD + ri;
        #pragma unroll
        for (int q = 0; q < 8; q++) {
            *(float4*)(op + (size_t)q * NORD)     = make_float4(acc[0][q], acc[1][q], acc[2][q], acc[3][q]);
            *(float4*)(op + (size_t)q * NORD + 4) = make_float4(acc[4][q], acc[5][q], acc[6][q], acc[7][q]);
        }
        __syncthreads();
    }
}

// ---------------------------------------------------------------------------
extern "C" void kernel_launch(void* const* d_in, const int* in_sizes, int n_in,
                              void* d_out, int out_size)
{
    const float* inp = (const float*)d_in[0];   // (L, BATCH)
    const float* A   = (const float*)d_in[1];   // (L, N, N)
    const float* Bv  = (const float*)d_in[2];   // (L, N)
    float* out = (float*)d_out;                 // (L, BATCH, N)

    cudaFuncSetAttribute(phase3_kernel, cudaFuncAttributeMaxDynamicSharedMemorySize, P3_SMEM);

    phase1_kernel<<<CCH, 256>>>(A, Bv, inp);
    phase2_kernel<<<BATCH / 4, 256>>>();
    phase3_kernel<<<CCH * G3, 128, P3_SMEM>>>(A, Bv, inp, out);
}

// round 4
// speedup vs baseline: 1.0887x; 1.0887x over previous
#include <cuda_runtime.h>
#include <cstdint>

#define L_SEQ 4096
#define BATCH 256
#define NORD  64
#define TCH   32
#define CCH   128   // L_SEQ / TCH
#define BS3   128   // batch per phase-3 CTA
#define G3    2     // BATCH / BS3

typedef unsigned long long ull;

__device__ __forceinline__ ull bcast2(float a) {
    ull r; asm("mov.b64 %0, {%1, %1};" : "=l"(r) : "f"(a)); return r;
}
__device__ __forceinline__ void ffma2(ull &d, ull a, ull b) {
    asm("fma.rn.f32x2 %0, %1, %2, %0;" : "+l"(d) : "l"(a), "l"(b));
}
__device__ __forceinline__ float2 unpack2(ull v) {
    float2 f; asm("mov.b64 {%0, %1}, %2;" : "=f"(f.x), "=f"(f.y) : "l"(v)); return f;
}

// Scratch (static device globals: no allocations allowed)
__device__ float g_P[(size_t)CCH * NORD * NORD];   // [c][i][j]  row-major P_c   2 MB
__device__ float g_S[(size_t)CCH * BATCH * NORD];  // [c][b][i]  chunk sources   8 MB
__device__ float g_X[(size_t)CCH * BATCH * NORD];  // [c][b][i]  boundary states 8 MB

// ---------------------------------------------------------------------------
// Phase 1: per chunk c (backward over t, Pt starts as Identity):
//   w_t = (Prod_{tau>t} A_tau) B_t ;  P_c = Prod_t A_t
// then S_c[b] = sum_t inputs[t,b] * w_t.
// Pt TRANSPOSED in smem: Pt[k][i] = P[i][k].  Packed FFMA2 along i.
// ---------------------------------------------------------------------------
__global__ __launch_bounds__(256) void phase1_kernel(
    const float* __restrict__ A, const float* __restrict__ Bv,
    const float* __restrict__ inp)
{
    __shared__ float Pt[NORD * NORD];
    __shared__ float As[NORD * NORD];
    __shared__ float Bs[NORD];
    __shared__ float W[TCH][NORD];

    const int c = blockIdx.x, tid = threadIdx.x;
    const int t0 = c * TCH;
    const int ri = (tid & 15) * 4;   // i-tile
    const int cj = (tid >> 4) * 4;   // j-tile

    // init: Pt = Identity; stage A,B for t = TCH-1
    for (int idx = tid; idx < NORD * NORD; idx += 256)
        Pt[idx] = ((idx >> 6) == (idx & 63)) ? 1.f : 0.f;
    {
        const float4* A4 = (const float4*)(A + (size_t)(t0 + TCH - 1) * (NORD * NORD));
        float4* As4 = (float4*)As;
        #pragma unroll
        for (int q = 0; q < 4; q++) As4[tid + q * 256] = A4[tid + q * 256];
        if (tid < 16)
            ((float4*)Bs)[tid] = ((const float4*)(Bv + (size_t)(t0 + TCH - 1) * NORD))[tid];
    }
    __syncthreads();

    #pragma unroll 1
    for (int t = TCH - 1; t >= 0; --t) {
        // prefetch next (earlier) A and B into registers
        float4 apf0, apf1, apf2, apf3, bpf;
        if (t > 0) {
            const float4* An = (const float4*)(A + (size_t)(t0 + t - 1) * (NORD * NORD));
            apf0 = An[tid]; apf1 = An[tid + 256]; apf2 = An[tid + 512]; apf3 = An[tid + 768];
            if (tid < 16) bpf = ((const float4*)(Bv + (size_t)(t0 + t - 1) * NORD))[tid];
        }

        // w_t[i] = sum_k Pt[k][i] * B_t[k]   (P BEFORE update => suffix product)
        float wacc = 0.f;
        if (tid < NORD) {
            #pragma unroll
            for (int k = 0; k < NORD; k++) wacc += Pt[k * NORD + tid] * Bs[k];
        }

        // Qt[j][i] = sum_k Pt[k][i] * A_t[k][j]  (P <- P @ A_t, kept transposed)
        ull acc2[4][2];
        #pragma unroll
        for (int jj = 0; jj < 4; jj++) { acc2[jj][0] = 0ull; acc2[jj][1] = 0ull; }

        #pragma unroll 8
        for (int k = 0; k < NORD; k++) {
            ulonglong2 p = *(const ulonglong2*)&Pt[k * NORD + ri];
            float4 a = *(const float4*)&As[k * NORD + cj];
            ull b0 = bcast2(a.x), b1 = bcast2(a.y), b2 = bcast2(a.z), b3 = bcast2(a.w);
            ffma2(acc2[0][0], b0, p.x); ffma2(acc2[0][1], b0, p.y);
            ffma2(acc2[1][0], b1, p.x); ffma2(acc2[1][1], b1, p.y);
            ffma2(acc2[2][0], b2, p.x); ffma2(acc2[2][1], b2, p.y);
            ffma2(acc2[3][0], b3, p.x); ffma2(acc2[3][1], b3, p.y);
        }
        __syncthreads();           // done reading Pt, As, Bs

        if (tid < NORD) W[t][tid] = wacc;
        if (t > 0) {
            #pragma unroll
            for (int jj = 0; jj < 4; jj++)
                *(ulonglong2*)&Pt[(cj + jj) * NORD + ri] =
                    make_ulonglong2(acc2[jj][0], acc2[jj][1]);
            float4* As4 = (float4*)As;
            As4[tid] = apf0; As4[tid + 256] = apf1; As4[tid + 512] = apf2; As4[tid + 768] = apf3;
            if (tid < 16) ((float4*)Bs)[tid] = bpf;
        } else {
            // final product: write g_P[c] row-major [i][j] straight from registers
            float f[4][4];
            #pragma unroll
            for (int jj = 0; jj < 4; jj++) {
                float2 v0 = unpack2(acc2[jj][0]); f[jj][0] = v0.x; f[jj][1] = v0.y;
                float2 v1 = unpack2(acc2[jj][1]); f[jj][2] = v1.x; f[jj][3] = v1.y;
            }
            float* gp = g_P + (size_t)c * (NORD * NORD);
            #pragma unroll
            for (int ii = 0; ii < 4; ii++)
                *(float4*)&gp[(ri + ii) * NORD + cj] =
                    make_float4(f[0][ii], f[1][ii], f[2][ii], f[3][ii]);
        }
        __syncthreads();
    }

    // S_c[b][i] = sum_t W[t][i] * inputs[t0+t][b]   (thread = batch b)
    {
        float u[TCH];
        #pragma unroll
        for (int tt = 0; tt < TCH; tt++) u[tt] = inp[(size_t)(t0 + tt) * BATCH + tid];
        float* sp = g_S + ((size_t)c * BATCH + tid) * NORD;
        #pragma unroll
        for (int half = 0; half < 2; half++) {
            ull acc[16];
            #pragma unroll
            for (int m = 0; m < 16; m++) acc[m] = 0ull;
            #pragma unroll 4
            for (int tt = 0; tt < TCH; tt++) {
                ull ub = bcast2(u[tt]);
                const ull* wrow = (const ull*)&W[tt][half * 32];
                #pragma unroll
                for (int m = 0; m < 16; m++) ffma2(acc[m], ub, wrow[m]);
            }
            #pragma unroll
            for (int m2 = 0; m2 < 8; m2++)
                *(ulonglong2*)&sp[half * 32 + m2 * 4] =
                    make_ulonglong2(acc[2 * m2], acc[2 * m2 + 1]);
        }
    }
}

// ---------------------------------------------------------------------------
// Phase 2: sequential over chunks:  X_c = P_c @ X_{c-1} + S_c
// 64 CTAs x 4 batches, 256 threads: thread = (i = tid>>2, bb = tid&3).
// P rows broadcast across the 4 batch lanes of each quad; j-packed FFMA2.
// Double-buffered P and x in smem; register prefetch; ONE barrier per step.
// ---------------------------------------------------------------------------
#define P2PAD 68
__global__ __launch_bounds__(256) void phase2_kernel()
{
    __shared__ float Ps[2][NORD * P2PAD];
    __shared__ float xsm[2][4][NORD];

    const int tid = threadIdx.x;
    const int b0 = blockIdx.x * 4;
    const int i  = tid >> 2;
    const int bb = tid & 3;

    // preload P for c=0, x = 0
    {
        const float4* gp = (const float4*)g_P;
        #pragma unroll
        for (int q = 0; q < 4; q++) {
            int f = tid + q * 256;              // float4 index 0..1023
            int ii = f >> 4, j4 = f & 15;
            *(float4*)&Ps[0][ii * P2PAD + j4 * 4] = gp[f];
        }
        xsm[0][bb][i] = 0.f;
    }
    float s_cur = g_S[((size_t)b0 + bb) * NORD + i];
    __syncthreads();

    int cur = 0;
    #pragma unroll 1
    for (int c = 0; c < CCH; c++) {
        float4 pf0, pf1, pf2, pf3; float s_nxt = 0.f;
        if (c + 1 < CCH) {
            const float4* gp = (const float4*)(g_P + (size_t)(c + 1) * (NORD * NORD));
            pf0 = gp[tid]; pf1 = gp[tid + 256]; pf2 = gp[tid + 512]; pf3 = gp[tid + 768];
            s_nxt = g_S[((size_t)(c + 1) * BATCH + b0 + bb) * NORD + i];
        }

        // acc = S + P[i][:] . x[bb][:]   (j-packed pairs, 4 chains)
        ull a0 = 0ull, a1 = 0ull, a2 = 0ull, a3 = 0ull;
        const float* prow = &Ps[cur][i * P2PAD];
        const float* xrow = &xsm[cur][bb][0];
        #pragma unroll
        for (int j8 = 0; j8 < 8; j8++) {
            ulonglong2 p0 = *(const ulonglong2*)(prow + j8 * 8);
            ulonglong2 p1 = *(const ulonglong2*)(prow + j8 * 8 + 4);
            ulonglong2 x0 = *(const ulonglong2*)(xrow + j8 * 8);
            ulonglong2 x1 = *(const ulonglong2*)(xrow + j8 * 8 + 4);
            ffma2(a0, p0.x, x0.x); ffma2(a1, p0.y, x0.y);
            ffma2(a2, p1.x, x1.x); ffma2(a3, p1.y, x1.y);
        }
        float2 f0 = unpack2(a0), f1 = unpack2(a1), f2 = unpack2(a2), f3 = unpack2(a3);
        float acc = s_cur + ((f0.x + f0.y) + (f1.x + f1.y)) + ((f2.x + f2.y) + (f3.x + f3.y));

        const int nxt = cur ^ 1;
        xsm[nxt][bb][i] = acc;
        g_X[((size_t)c * BATCH + b0 + bb) * NORD + i] = acc;
        if (c + 1 < CCH) {
            #pragma unroll
            for (int q = 0; q < 4; q++) {
                float4 pv = (q == 0) ? pf0 : (q == 1) ? pf1 : (q == 2) ? pf2 : pf3;
                int f = tid + q * 256;
                int ii = f >> 4, j4 = f & 15;
                *(float4*)&Ps[nxt][ii * P2PAD + j4 * 4] = pv;
            }
        }
        s_cur = s_nxt;
        __syncthreads();
        cur = nxt;
    }
}

// ---------------------------------------------------------------------------
// Phase 3: per (chunk, batch-half): scan TCH steps with correct init X_{c-1},
// writing all outputs. Per-step: Xnew(64x128) = A_t @ X + B_t (x) u_t.
// 128 threads, 8x8 tiles, FFMA2 packed along batch; A double-buffered via regs.
// ---------------------------------------------------------------------------
#define P3_APAD 68
#define P3_SMEM ((NORD * P3_APAD + NORD * BS3 + NORD) * 4)

__device__ __forceinline__ void p3_stage_A(float* As, const float4* apf, int tid) {
    #pragma unroll
    for (int q = 0; q < 8; q++) {
        int f = tid + q * 128;              // float4 index: i = f>>4, j = 4*(f&15)
        int i = f >> 4, j = (f & 15) * 4;
        float4 v = apf[q];
        As[(j + 0) * P3_APAD + i] = v.x;
        As[(j + 1) * P3_APAD + i] = v.y;
        As[(j + 2) * P3_APAD + i] = v.z;
        As[(j + 3) * P3_APAD + i] = v.w;
    }
}

__global__ __launch_bounds__(128) void phase3_kernel(
    const float* __restrict__ A, const float* __restrict__ Bv,
    const float* __restrict__ inp, float* __restrict__ out)
{
    extern __shared__ float sm[];
    float* As = sm;                       // [64][68]  As[k][i] = A[i][k]
    float* xs = sm + NORD * P3_APAD;      // [64][128] xs[j][b]
    float* Bs = xs + NORD * BS3;          // [64]

    const int c  = blockIdx.x >> 1;
    const int b0 = (blockIdx.x & 1) * BS3;
    const int tid = threadIdx.x;
    const int bi = (tid & 15) * 8;        // batch tile
    const int riq = (tid >> 4);
    const int ri = riq * 8;
    const int t0 = c * TCH;

    // stage A,B for t=0
    {
        const float4* A4 = (const float4*)(A + (size_t)t0 * (NORD * NORD));
        float4 apf[8];
        #pragma unroll
        for (int q = 0; q < 8; q++) apf[q] = A4[tid + q * 128];
        p3_stage_A(As, apf, tid);
        if (tid < 16) ((float4*)Bs)[tid] = ((const float4*)(Bv + (size_t)t0 * NORD))[tid];
    }

    // load initial state (transposed into [j][b])
    if (c == 0) {
        for (int idx = tid; idx < NORD * BS3; idx += 128) xs[idx] = 0.f;
    } else {
        const float4* Xp = (const float4*)(g_X + (((size_t)(c - 1)) * BATCH + b0 + tid) * NORD);
        #pragma unroll
        for (int j4 = 0; j4 < 16; j4++) {
            float4 v = Xp[j4];
            xs[(j4 * 4 + 0) * BS3 + tid] = v.x;
            xs[(j4 * 4 + 1) * BS3 + tid] = v.y;
            xs[(j4 * 4 + 2) * BS3 + tid] = v.z;
            xs[(j4 * 4 + 3) * BS3 + tid] = v.w;
        }
    }
    __syncthreads();

    #pragma unroll 1
    for (int t = 0; t < TCH; t++) {
        // prefetch next A,B
        float4 apf[8]; float4 bpf;
        if (t < TCH - 1) {
            const float4* An = (const float4*)(A + (size_t)(t0 + t + 1) * (NORD * NORD));
            #pragma unroll
            for (int q = 0; q < 8; q++) apf[q] = An[tid + q * 128];
            if (tid < 16) bpf = ((const float4*)(Bv + (size_t)(t0 + t + 1) * NORD))[tid];
        }

        ull acc2[8][4];
        #pragma unroll
        for (int r = 0; r < 8; r++)
            #pragma unroll
            for (int q = 0; q < 4; q++) acc2[r][q] = 0ull;

        const float4* As4 = (const float4*)As;
        #pragma unroll 8
        for (int k = 0; k < NORD; k++) {
            float4 a0 = As4[k * (P3_APAD / 4) + riq * 2];
            float4 a1 = As4[k * (P3_APAD / 4) + riq * 2 + 1];
            ulonglong2 x0 = *(const ulonglong2*)&xs[k * BS3 + bi];
            ulonglong2 x1 = *(const ulonglong2*)&xs[k * BS3 + bi + 4];
            float av[8] = {a0.x, a0.y, a0.z, a0.w, a1.x, a1.y, a1.z, a1.w};
            #pragma unroll
            for (int r = 0; r < 8; r++) {
                ull ab = bcast2(av[r]);
                ffma2(acc2[r][0], ab, x0.x); ffma2(acc2[r][1], ab, x0.y);
                ffma2(acc2[r][2], ab, x1.x); ffma2(acc2[r][3], ab, x1.y);
            }
        }

        // + B_t[i] * u_t[b]
        {
            const float* up = inp + (size_t)(t0 + t) * BATCH + b0 + bi;
            ulonglong2 u0 = *(const ulonglong2*)up;
            ulonglong2 u1 = *(const ulonglong2*)(up + 4);
            #pragma unroll
            for (int r = 0; r < 8; r++) {
                ull ab = bcast2(Bs[ri + r]);
                ffma2(acc2[r][0], ab, u0.x); ffma2(acc2[r][1], ab, u0.y);
                ffma2(acc2[r][2], ab, u1.x); ffma2(acc2[r][3], ab, u1.y);
            }
        }
        __syncthreads();   // done reading xs/As/Bs

        // update state
        #pragma unroll
        for (int r = 0; r < 8; r++) {
            *(ulonglong2*)&xs[(ri + r) * BS3 + bi]     = make_ulonglong2(acc2[r][0], acc2[r][1]);
            *(ulonglong2*)&xs[(ri + r) * BS3 + bi + 4] = make_ulonglong2(acc2[r][2], acc2[r][3]);
        }
        // write output x_t (unpack per q-pair)
        float* obase = out + (size_t)(t0 + t) * (BATCH * NORD) + (size_t)(b0 + bi) * NORD + ri;
        #pragma unroll
        for (int q2 = 0; q2 < 4; q2++) {
            float lo[8], hi[8];
            #pragma unroll
            for (int r = 0; r < 8; r++) {
                float2 v = unpack2(acc2[r][q2]);
                lo[r] = v.x; hi[r] = v.y;
            }
            float* op = obase + (size_t)(2 * q2) * NORD;
            *(float4*)op        = make_float4(lo[0], lo[1], lo[2], lo[3]);
            *(float4*)(op + 4)  = make_float4(lo[4], lo[5], lo[6], lo[7]);
            *(float4*)(op + NORD)     = make_float4(hi[0], hi[1], hi[2], hi[3]);
            *(float4*)(op + NORD + 4) = make_float4(hi[4], hi[5], hi[6], hi[7]);
        }

        if (t < TCH - 1) {
            p3_stage_A(As, apf, tid);
            if (tid < 16) ((float4*)Bs)[tid] = bpf;
        }
        __syncthreads();
    }
}

// ---------------------------------------------------------------------------
extern "C" void kernel_launch(void* const* d_in, const int* in_sizes, int n_in,
                              void* d_out, int out_size)
{
    const float* inp = (const float*)d_in[0];   // (L, BATCH)
    const float* A   = (const float*)d_in[1];   // (L, N, N)
    const float* Bv  = (const float*)d_in[2];   // (L, N)
    float* out = (float*)d_out;                 // (L, BATCH, N)

    cudaFuncSetAttribute(phase3_kernel, cudaFuncAttributeMaxDynamicSharedMemorySize, P3_SMEM);

    phase1_kernel<<<CCH, 256>>>(A, Bv, inp);
    phase2_kernel<<<BATCH / 4, 256>>>();
    phase3_kernel<<<CCH * G3, 128, P3_SMEM>>>(A, Bv, inp, out);
}